// round 13
// baseline (speedup 1.0000x reference)
#include <cuda_runtime.h>
#include <math.h>

// ---------------- packed f32x2 helpers (sm_103a FFMA2) ----------------
typedef unsigned long long u64;
__device__ __forceinline__ u64 pk2(float lo, float hi) {
    u64 r; asm("mov.b64 %0, {%1,%2};" : "=l"(r) : "f"(lo), "f"(hi)); return r;
}
__device__ __forceinline__ u64 ffma2(u64 a, u64 b, u64 c) {
    u64 d; asm("fma.rn.f32x2 %0, %1, %2, %3;" : "=l"(d) : "l"(a), "l"(b), "l"(c)); return d;
}
__device__ __forceinline__ float2 upk2(u64 v) {
    float2 f; asm("mov.b64 {%0,%1}, %2;" : "=f"(f.x), "=f"(f.y) : "l"(v)); return f;
}

// ---------------- static device scratch ----------------
__device__ float g_h1[(size_t)16*64*128*128];
__device__ float g_a [(size_t)16*128*64*64];
__device__ float g_b [(size_t)16*128*64*64];
__device__ float g_c [(size_t)16*32*64*64];
__device__ float g_z [(size_t)16*64*64*64];
__device__ float g_q [(size_t)16*64*64*64];
__device__ float g_c2[512];
__device__ int   g_counts[512];
__device__ float g_partial[256];

#define OFF_XREC   1
#define OFF_PERP   1048577
#define OFF_ENC    1048578
#define OFF_QUANT  34603010

// ============ 3x3 s1 p1 conv on 64x64; 8-row tile; thread = 2 rows x 8 oc ============
// Input tile stored in smem as replicated (v,v) float2 pairs -> LDS.64 lands a
// ready-packed FFMA2 operand (no per-ci MOV packing). Weights smem [ci][tap(9)][o(8)].
// Per-output chain: bias -> ci asc -> tap asc (bit-exact across rounds).
template<int CIN, bool RELU_IN, bool RELU_OUT, bool HAS_BIAS>
__global__ __launch_bounds__(256)
void conv3_t(const float* __restrict__ in, const float* __restrict__ w,
             const float* __restrict__ bias, float* __restrict__ out, int COUT)
{
    __shared__ u64 s_in[2][10*66];
    __shared__ __align__(16) float s_w[CIN*72];
    const int tid = threadIdx.x;
    const int tx = tid & 63, ty = tid >> 6;
    const int tile = blockIdx.x, n = blockIdx.y, ocg = blockIdx.z;

    for (int i = tid; i < CIN*72; i += 256) {
        int ci = i / 72, rem = i % 72, tap = rem >> 3, o = rem & 7;
        s_w[i] = w[((size_t)(ocg*8 + o) * CIN + ci) * 9 + tap];
    }
    const int ih0 = tile*8 - 1;
    const float* inN = in + (size_t)n * CIN * 4096;

    // hoisted staging offsets: elements tid, tid+256, tid+512 (660 total)
    int eoff[3];
#pragma unroll
    for (int k = 0; k < 3; ++k) {
        int i = tid + k*256;
        int r = i / 66, c = i % 66;
        int ih = ih0 + r, iw = c - 1;
        bool ok = (i < 660) && ((unsigned)ih < 64u) && ((unsigned)iw < 64u);
        eoff[k] = ok ? (ih*64 + iw) : -1;
    }

    {   // stage ci 0
        u64* sb = s_in[0];
#pragma unroll
        for (int k = 0; k < 3; ++k) {
            if (k < 2 || tid < 148) {
                float v = (eoff[k] >= 0) ? inN[eoff[k]] : 0.0f;
                if (RELU_IN) v = fmaxf(v, 0.0f);
                sb[tid + k*256] = pk2(v, v);
            }
        }
    }
    __syncthreads();

    u64 accp[2][4];  // [j][pair p], pair p covers o = 2p, 2p+1
#pragma unroll
    for (int p = 0; p < 4; ++p) {
        float b0 = HAS_BIAS ? __ldg(&bias[ocg*8+2*p])   : 0.0f;
        float b1 = HAS_BIAS ? __ldg(&bias[ocg*8+2*p+1]) : 0.0f;
        u64 bp = pk2(b0, b1);
        accp[0][p] = bp; accp[1][p] = bp;
    }

#pragma unroll 1
    for (int ci = 0; ci < CIN; ++ci) {
        if (ci + 1 < CIN) {
            const float* ip = inN + (size_t)(ci+1) * 4096;
            u64* sb = s_in[(ci+1)&1];
#pragma unroll
            for (int k = 0; k < 3; ++k) {
                if (k < 2 || tid < 148) {
                    float v = (eoff[k] >= 0) ? ip[eoff[k]] : 0.0f;
                    if (RELU_IN) v = fmaxf(v, 0.0f);
                    sb[tid + k*256] = pk2(v, v);
                }
            }
        }
        const u64* sb = s_in[ci&1];
        u64 ivp[12];
#pragma unroll
        for (int r = 0; r < 4; ++r)
#pragma unroll
            for (int c = 0; c < 3; ++c)
                ivp[r*3+c] = sb[(ty*2+r)*66 + tx + c];
        const float* wp = s_w + ci*72;
#pragma unroll
        for (int t = 0; t < 9; ++t) {
            ulonglong2 wA = *(const ulonglong2*)(wp + t*8);      // pairs (o0,o1),(o2,o3)
            ulonglong2 wB = *(const ulonglong2*)(wp + t*8 + 4);  // pairs (o4,o5),(o6,o7)
            const int r = t / 3, c = t % 3;
#pragma unroll
            for (int j = 0; j < 2; ++j) {
                u64 vv = ivp[(j+r)*3+c];
                accp[j][0] = ffma2(vv, wA.x, accp[j][0]);
                accp[j][1] = ffma2(vv, wA.y, accp[j][1]);
                accp[j][2] = ffma2(vv, wB.x, accp[j][2]);
                accp[j][3] = ffma2(vv, wB.y, accp[j][3]);
            }
        }
        __syncthreads();
    }

    const int ohb = tile*8 + ty*2;
#pragma unroll
    for (int j = 0; j < 2; ++j)
#pragma unroll
        for (int p = 0; p < 4; ++p) {
            float2 v = upk2(accp[j][p]);
            if (RELU_OUT) { v.x = fmaxf(v.x, 0.0f); v.y = fmaxf(v.y, 0.0f); }
            out[(((size_t)n * COUT + ocg*8+2*p)   * 64 + ohb + j) * 64 + tx] = v.x;
            out[(((size_t)n * COUT + ocg*8+2*p+1) * 64 + ohb + j) * 64 + tx] = v.y;
        }
}

// ============ 4x4 s2 p1 conv, 64ch 128x128 -> 128ch 64x64 (ew2) ============
// replicated-pair input smem; weight staging [tap(16)][o(8)]; hoisted offsets
__global__ __launch_bounds__(256)
void conv4s2_t(const float* __restrict__ in, const float* __restrict__ w,
               const float* __restrict__ bias, float* __restrict__ out)
{
    __shared__ u64 s_in[2][18*130];
    __shared__ __align__(16) float s_wc[2][128];
    const int tid = threadIdx.x;
    const int tx = tid & 63, ty = tid >> 6;
    const int tile = blockIdx.x, n = blockIdx.y, ocg = blockIdx.z;
    const int ih0 = 16*tile - 1;
    const float* inN = in + (size_t)n * 64 * 16384;

    // 18*130 = 2340 elements; k<9 full, k=9 partial (tid<36)
    int eoff[10];
#pragma unroll
    for (int k = 0; k < 10; ++k) {
        int i = tid + k*256;
        int r = i / 130, c = i % 130;
        int ih = ih0 + r, iw = c - 1;
        bool ok = (k < 9 || tid < 36) && ((unsigned)ih < 128u) && ((unsigned)iw < 128u);
        eoff[k] = ok ? (ih*128 + iw) : -1;
    }

    {   // stage ci 0
        u64* sb = s_in[0];
#pragma unroll
        for (int k = 0; k < 10; ++k)
            if (k < 9 || tid < 36) {
                float v = (eoff[k] >= 0) ? inN[eoff[k]] : 0.0f;
                sb[tid + k*256] = pk2(v, v);
            }
    }
    if (tid < 128) {
        int tap = tid >> 3, o = tid & 7;
        s_wc[0][tid] = w[((size_t)(ocg*8 + o) * 64 + 0) * 16 + tap];
    }
    __syncthreads();

    u64 accp[2][4];
#pragma unroll
    for (int p = 0; p < 4; ++p) {
        u64 bp = pk2(__ldg(&bias[ocg*8+2*p]), __ldg(&bias[ocg*8+2*p+1]));
        accp[0][p] = bp; accp[1][p] = bp;
    }

#pragma unroll 1
    for (int ci = 0; ci < 64; ++ci) {
        if (ci + 1 < 64) {
            const float* ip = inN + (size_t)(ci+1) * 16384;
            u64* sb = s_in[(ci+1)&1];
#pragma unroll
            for (int k = 0; k < 10; ++k)
                if (k < 9 || tid < 36) {
                    float v = (eoff[k] >= 0) ? ip[eoff[k]] : 0.0f;
                    sb[tid + k*256] = pk2(v, v);
                }
            if (tid < 128) {
                int tap = tid >> 3, o = tid & 7;
                s_wc[(ci+1)&1][tid] = w[((size_t)(ocg*8 + o) * 64 + ci+1) * 16 + tap];
            }
        }
        const u64* sb = s_in[ci&1];
        const float* wc = s_wc[ci&1];
#pragma unroll
        for (int kh = 0; kh < 4; ++kh) {
            u64 ivp[8];
#pragma unroll
            for (int j = 0; j < 2; ++j)
#pragma unroll
                for (int kw = 0; kw < 4; ++kw)
                    ivp[j*4+kw] = sb[(2*(ty*2+j)+kh)*130 + 2*tx + kw];
#pragma unroll
            for (int kw = 0; kw < 4; ++kw) {
                const int t = kh*4 + kw;
                ulonglong2 wA = *(const ulonglong2*)(wc + t*8);
                ulonglong2 wB = *(const ulonglong2*)(wc + t*8 + 4);
#pragma unroll
                for (int j = 0; j < 2; ++j) {
                    u64 vv = ivp[j*4+kw];
                    accp[j][0] = ffma2(vv, wA.x, accp[j][0]);
                    accp[j][1] = ffma2(vv, wA.y, accp[j][1]);
                    accp[j][2] = ffma2(vv, wB.x, accp[j][2]);
                    accp[j][3] = ffma2(vv, wB.y, accp[j][3]);
                }
            }
        }
        __syncthreads();
    }

    const int ohb = tile*8 + ty*2;
#pragma unroll
    for (int j = 0; j < 2; ++j)
#pragma unroll
        for (int p = 0; p < 4; ++p) {
            float2 v = upk2(accp[j][p]);
            out[(((size_t)n * 128 + ocg*8+2*p)   * 64 + ohb + j) * 64 + tx] = fmaxf(v.x, 0.0f);
            out[(((size_t)n * 128 + ocg*8+2*p+1) * 64 + ohb + j) * 64 + tx] = fmaxf(v.y, 0.0f);
        }
}

// ============ 4x4 s2 p1 conv, 1ch 256x256 -> 64ch 128x128 (ew1) ============
__global__ __launch_bounds__(256)
void ew1_t(const float* __restrict__ in, const float* __restrict__ w,
           const float* __restrict__ bias, float* __restrict__ out)
{
    __shared__ float s_in[34*130];
    __shared__ float s_w[128];
    const int tid = threadIdx.x;
    const int tx = tid & 63, ty = tid >> 6;
    const int rt = blockIdx.x >> 1, ct = blockIdx.x & 1;
    const int n = blockIdx.y, ocg = blockIdx.z;
    const int ih0 = 32*rt - 1, iw0 = 128*ct - 1;
    const float* ip = in + (size_t)n * 65536;

    for (int i = tid; i < 34*130; i += 256) {
        int r = i / 130, c = i % 130;
        int ih = ih0 + r, iw = iw0 + c;
        s_in[i] = ((unsigned)ih < 256u && (unsigned)iw < 256u) ? ip[ih*256+iw] : 0.0f;
    }
    if (tid < 128) s_w[tid] = w[(ocg*8 + (tid>>4))*16 + (tid&15)];
    __syncthreads();

    float acc[32];
#pragma unroll
    for (int o = 0; o < 8; ++o) {
        float b0 = __ldg(&bias[ocg*8+o]);
#pragma unroll
        for (int j = 0; j < 4; ++j) acc[j*8+o] = b0;
    }
#pragma unroll
    for (int kh = 0; kh < 4; ++kh) {
        float iv[16];
#pragma unroll
        for (int j = 0; j < 4; ++j)
#pragma unroll
            for (int kw = 0; kw < 4; ++kw)
                iv[j*4+kw] = s_in[(2*(ty*4+j)+kh)*130 + 2*tx + kw];
#pragma unroll
        for (int o = 0; o < 8; ++o) {
            float v0 = s_w[o*16+kh*4+0], v1 = s_w[o*16+kh*4+1],
                  v2 = s_w[o*16+kh*4+2], v3 = s_w[o*16+kh*4+3];
#pragma unroll
            for (int j = 0; j < 4; ++j) {
                float a = acc[j*8+o];
                a = fmaf(iv[j*4+0], v0, a);
                a = fmaf(iv[j*4+1], v1, a);
                a = fmaf(iv[j*4+2], v2, a);
                a = fmaf(iv[j*4+3], v3, a);
                acc[j*8+o] = a;
            }
        }
    }
    const int ohb = rt*16 + ty*4;
#pragma unroll
    for (int j = 0; j < 4; ++j)
#pragma unroll
        for (int o = 0; o < 8; ++o)
            out[(((size_t)n * 64 + ocg*8+o) * 128 + ohb + j) * 128 + ct*64 + tx] = fmaxf(acc[j*8+o], 0.0f);
}

// ============ convT 4x4 s2 p1, 128ch 64x64 -> 64ch 128x128 (dtw1) ============
// replicated-pair input smem; weights [ci][tap(8)][o(4)]; hoisted offsets
__global__ __launch_bounds__(256)
void convT1_t(const float* __restrict__ in, const float* __restrict__ w,
              const float* __restrict__ bias, float* __restrict__ out)
{
    __shared__ u64 s_in[2][10*66];
    __shared__ __align__(16) float s_w[128*32];
    const int tid = threadIdx.x;
    const int tx = tid & 63, ty = tid >> 6;
    const int tile = blockIdx.x, n = blockIdx.y;
    const int py = blockIdx.z & 1, ocg = blockIdx.z >> 1;

    for (int i = tid; i < 128*32; i += 256) {
        int ci = i >> 5, rem = i & 31, tap = rem >> 2, o = rem & 3;
        int a = tap >> 2, kw = tap & 3;
        int kh = py ? (a ? 0 : 2) : (a ? 1 : 3);
        s_w[i] = w[((size_t)ci * 64 + ocg*4 + o) * 16 + kh*4 + kw];
    }
    const int ih0 = tile*8 - 1;
    const float* inN = in + (size_t)n * 128 * 4096;

    int eoff[3];
#pragma unroll
    for (int k = 0; k < 3; ++k) {
        int i = tid + k*256;
        int r = i / 66, c = i % 66;
        int ih = ih0 + r, iw = c - 1;
        bool ok = (i < 660) && ((unsigned)ih < 64u) && ((unsigned)iw < 64u);
        eoff[k] = ok ? (ih*64 + iw) : -1;
    }

    {   // stage ci 0
        u64* sb = s_in[0];
#pragma unroll
        for (int k = 0; k < 3; ++k)
            if (k < 2 || tid < 148) {
                float v = (eoff[k] >= 0) ? inN[eoff[k]] : 0.0f;
                sb[tid + k*256] = pk2(v, v);
            }
    }
    __syncthreads();

    u64 accp[4][2]; // [(j*2+px)][pair p] p covers o=2p,2p+1
    {
        u64 b01 = pk2(__ldg(&bias[ocg*4+0]), __ldg(&bias[ocg*4+1]));
        u64 b23 = pk2(__ldg(&bias[ocg*4+2]), __ldg(&bias[ocg*4+3]));
#pragma unroll
        for (int jp = 0; jp < 4; ++jp) { accp[jp][0] = b01; accp[jp][1] = b23; }
    }

#pragma unroll 1
    for (int ci = 0; ci < 128; ++ci) {
        if (ci + 1 < 128) {
            const float* ip = inN + (size_t)(ci+1) * 4096;
            u64* sb = s_in[(ci+1)&1];
#pragma unroll
            for (int k = 0; k < 3; ++k)
                if (k < 2 || tid < 148) {
                    float v = (eoff[k] >= 0) ? ip[eoff[k]] : 0.0f;
                    sb[tid + k*256] = pk2(v, v);
                }
        }
        const u64* sb = s_in[ci&1];
        const int rb = ty*2 + py;
        u64 ivp[9];
#pragma unroll
        for (int r = 0; r < 3; ++r)
#pragma unroll
            for (int c = 0; c < 3; ++c)
                ivp[r*3+c] = sb[(rb+r)*66 + tx + c];
        const float* wp = s_w + ci*32;
#pragma unroll
        for (int tap = 0; tap < 8; ++tap) {
            const int a = tap >> 2, kw = tap & 3;
            const int px  = (kw & 1) ? 0 : 1;
            const int col = (kw & 1) ? ((3-kw) >> 1) : ((2-kw) >> 1) + 1;
            ulonglong2 wv = *(const ulonglong2*)(wp + tap*4);
#pragma unroll
            for (int j = 0; j < 2; ++j) {
                u64 vv = ivp[(j+a)*3 + col];
                accp[j*2+px][0] = ffma2(vv, wv.x, accp[j*2+px][0]);
                accp[j*2+px][1] = ffma2(vv, wv.y, accp[j*2+px][1]);
            }
        }
        __syncthreads();
    }

#pragma unroll
    for (int j = 0; j < 2; ++j) {
        int oh = 2*(tile*8 + ty*2 + j) + py;
        float2 p0a = upk2(accp[j*2+0][0]), p0b = upk2(accp[j*2+0][1]);
        float2 p1a = upk2(accp[j*2+1][0]), p1b = upk2(accp[j*2+1][1]);
        float vx0[4] = {p0a.x, p0a.y, p0b.x, p0b.y};
        float vx1[4] = {p1a.x, p1a.y, p1b.x, p1b.y};
#pragma unroll
        for (int o = 0; o < 4; ++o) {
            float2 v;
            v.x = fmaxf(vx0[o], 0.0f);
            v.y = fmaxf(vx1[o], 0.0f);
            *(float2*)&out[(((size_t)n * 64 + ocg*4+o) * 128 + oh) * 128 + 2*tx] = v;
        }
    }
}

// ============ convT 4x4 s2 p1, 64ch 128x128 -> 1ch 256x256 (dtw2) ============
__global__ __launch_bounds__(256)
void convT2_t(const float* __restrict__ in, const float* __restrict__ w,
              const float* __restrict__ bias, float* __restrict__ out)
{
    __shared__ float s_in[2][10*130];
    __shared__ __align__(16) float s_w[64*8];
    const int tid = threadIdx.x;
    const int tx = tid & 127, ty = tid >> 7;
    const int tile = blockIdx.x, n = blockIdx.y, py = blockIdx.z;

    for (int i = tid; i < 64*8; i += 256) {
        int ci = i >> 3, a = (i >> 2) & 1, kw = i & 3;
        int kh = py ? (a ? 0 : 2) : (a ? 1 : 3);
        s_w[i] = w[(size_t)ci * 16 + kh*4 + kw];
    }
    const int ih0 = tile*8 - 1;
    const float* inN = in + (size_t)n * 64 * 16384;

    // 10*130 = 1300 elements; k<5 full, k=5 partial (tid<20)
    int eoff[6];
#pragma unroll
    for (int k = 0; k < 6; ++k) {
        int i = tid + k*256;
        int r = i / 130, c = i % 130;
        int ih = ih0 + r, iw = c - 1;
        bool ok = (k < 5 || tid < 20) && ((unsigned)ih < 128u) && ((unsigned)iw < 128u);
        eoff[k] = ok ? (ih*128 + iw) : -1;
    }

    {   // stage ci 0
        float* sb = s_in[0];
#pragma unroll
        for (int k = 0; k < 6; ++k)
            if (k < 5 || tid < 20)
                sb[tid + k*256] = (eoff[k] >= 0) ? inN[eoff[k]] : 0.0f;
    }
    __syncthreads();

    float b0 = __ldg(&bias[0]);
    float acc[8];
#pragma unroll
    for (int i = 0; i < 8; ++i) acc[i] = b0;

#pragma unroll 1
    for (int ci = 0; ci < 64; ++ci) {
        if (ci + 1 < 64) {
            const float* ip = inN + (size_t)(ci+1) * 16384;
            float* sb = s_in[(ci+1)&1];
#pragma unroll
            for (int k = 0; k < 6; ++k)
                if (k < 5 || tid < 20)
                    sb[tid + k*256] = (eoff[k] >= 0) ? ip[eoff[k]] : 0.0f;
        }
        const float* sb = s_in[ci&1];
        const int rb = ty*4 + py;
        float iv[15];
#pragma unroll
        for (int r = 0; r < 5; ++r)
#pragma unroll
            for (int c = 0; c < 3; ++c)
                iv[r*3+c] = sb[(rb+r)*130 + tx + c];
        float4 lv = *(const float4*)(s_w + ci*8);
        float4 hv = *(const float4*)(s_w + ci*8 + 4);
#pragma unroll
        for (int j = 0; j < 4; ++j) {
            float a0 = acc[j*2+0];
            a0 = fmaf(iv[j*3+0],     lv.w, a0);
            a0 = fmaf(iv[j*3+1],     lv.y, a0);
            a0 = fmaf(iv[(j+1)*3+0], hv.w, a0);
            a0 = fmaf(iv[(j+1)*3+1], hv.y, a0);
            acc[j*2+0] = a0;
            float a1 = acc[j*2+1];
            a1 = fmaf(iv[j*3+1],     lv.z, a1);
            a1 = fmaf(iv[j*3+2],     lv.x, a1);
            a1 = fmaf(iv[(j+1)*3+1], hv.z, a1);
            a1 = fmaf(iv[(j+1)*3+2], hv.x, a1);
            acc[j*2+1] = a1;
        }
        __syncthreads();
    }

#pragma unroll
    for (int j = 0; j < 4; ++j) {
        int oh = 2*(tile*8 + ty*4 + j) + py;
        size_t base = (size_t)n * 65536 + (size_t)oh * 256 + 2*tx;
        out[base]     = acc[j*2+0];
        out[base + 1] = acc[j*2+1];
    }
}

// ============ 1x1 conv; thread = 1 px x 16 oc; FFMA2 over o-pairs ============
template<int CIN, bool RELU_IN, bool HAS_BIAS, bool ADD_RES>
__global__ __launch_bounds__(256)
void conv1x1_t(const float* __restrict__ in, const float* __restrict__ w,
               const float* __restrict__ bias, const float* __restrict__ res,
               float* __restrict__ out, int COUT)
{
    __shared__ __align__(16) float s_w[CIN*16];
    const int tid = threadIdx.x;
    const int n = blockIdx.y, ocg = blockIdx.z;
    for (int i = tid; i < CIN*16; i += 256)
        s_w[i] = w[(size_t)(ocg*16 + (i&15)) * CIN + (i>>4)];
    __syncthreads();

    const int hw = blockIdx.x*256 + tid;
    u64 accp[8];
#pragma unroll
    for (int p = 0; p < 8; ++p) {
        float b0 = HAS_BIAS ? __ldg(&bias[ocg*16+2*p])   : 0.0f;
        float b1 = HAS_BIAS ? __ldg(&bias[ocg*16+2*p+1]) : 0.0f;
        accp[p] = pk2(b0, b1);
    }
    const float* ip = in + ((size_t)n * CIN << 12) + hw;
#pragma unroll 4
    for (int ci = 0; ci < CIN; ++ci) {
        float v = ip[(size_t)ci << 12];
        if (RELU_IN) v = fmaxf(v, 0.0f);
        u64 vv = pk2(v, v);
        const ulonglong2* wr = (const ulonglong2*)(s_w + ci*16);
        ulonglong2 w0 = wr[0], w1 = wr[1], w2 = wr[2], w3 = wr[3];
        accp[0] = ffma2(vv, w0.x, accp[0]);
        accp[1] = ffma2(vv, w0.y, accp[1]);
        accp[2] = ffma2(vv, w1.x, accp[2]);
        accp[3] = ffma2(vv, w1.y, accp[3]);
        accp[4] = ffma2(vv, w2.x, accp[4]);
        accp[5] = ffma2(vv, w2.y, accp[5]);
        accp[6] = ffma2(vv, w3.x, accp[6]);
        accp[7] = ffma2(vv, w3.y, accp[7]);
    }
#pragma unroll
    for (int p = 0; p < 8; ++p) {
        float2 v = upk2(accp[p]);
        size_t oi0 = (((size_t)n * COUT + ocg*16+2*p)   << 12) + hw;
        size_t oi1 = (((size_t)n * COUT + ocg*16+2*p+1) << 12) + hw;
        float v0 = v.x, v1 = v.y;
        if (ADD_RES) { v0 += res[oi0]; v1 += res[oi1]; }
        out[oi0] = v0;
        out[oi1] = v1;
    }
}

// ---------------- VQ ----------------
__global__ void vq_prep(const float* __restrict__ cb)
{
    int k = blockIdx.x * blockDim.x + threadIdx.x;
    if (k < 512) {
        float s = 0.0f;
        const float* c = cb + k * 64;
#pragma unroll
        for (int d = 0; d < 64; ++d) s = fmaf(c[d], c[d], s);
        g_c2[k] = s;
        g_counts[k] = 0;
    }
}

__global__ void fill_zero2(float2* __restrict__ p, int n2)
{
    int i = blockIdx.x * blockDim.x + threadIdx.x;
    if (i < n2) p[i] = make_float2(0.0f, 0.0f);
}

// merged argmin + quantize (bit-exact tie-break preserved)
__global__ void vq_main(const float* __restrict__ cb, float* __restrict__ out_enc,
                        float* __restrict__ out_quant)
{
    __shared__ float sc[64 * 64];
    __shared__ float sc2[64];
    __shared__ int   hist[512];
    __shared__ float red[256];
    int tid = threadIdx.x;
    for (int i = tid; i < 512; i += 256) hist[i] = 0;

    int r  = blockIdx.x * 256 + tid;
    int n  = r >> 12;
    int hw = r & 4095;
    size_t zbase = (size_t)n * 64 * 4096 + hw;
    const float* zp = g_z + zbase;

    float zr[64];
#pragma unroll
    for (int d = 0; d < 64; ++d) zr[d] = zp[(size_t)d * 4096];

    float z2 = 0.0f;
#pragma unroll
    for (int d = 0; d < 64; ++d) z2 = fmaf(zr[d], zr[d], z2);

    float best = 3.4e38f;
    int bi = 0;
    for (int chunk = 0; chunk < 8; ++chunk) {
        __syncthreads();
        for (int i = tid; i < 4096; i += 256) sc[i] = cb[chunk * 4096 + i];
        if (tid < 64) sc2[tid] = g_c2[chunk * 64 + tid];
        __syncthreads();
        for (int c = 0; c < 64; ++c) {
            const float4* cv = (const float4*)&sc[c * 64];
            float d0 = 0, d1 = 0, d2 = 0, d3 = 0;
#pragma unroll
            for (int j = 0; j < 16; ++j) {
                float4 v = cv[j];
                d0 = fmaf(v.x, zr[4 * j + 0], d0);
                d1 = fmaf(v.y, zr[4 * j + 1], d1);
                d2 = fmaf(v.z, zr[4 * j + 2], d2);
                d3 = fmaf(v.w, zr[4 * j + 3], d3);
            }
            float dot = (d0 + d1) + (d2 + d3);
            float dist = __fadd_rn(__fadd_rn(z2, sc2[c]), -2.0f * dot);
            if (dist < best) { best = dist; bi = chunk * 64 + c; }
        }
    }
    atomicAdd(&hist[bi], 1);

    float* qp = g_q + zbase;
    float* oq = out_quant + zbase;
    const float* ck = cb + bi * 64;
    float sse = 0.0f;
#pragma unroll
    for (int d = 0; d < 64; ++d) {
        float qv = __ldg(&ck[d]);
        qp[(size_t)d * 4096] = qv;
        oq[(size_t)d * 4096] = qv;
        float df = qv - zr[d];
        sse = fmaf(df, df, sse);
    }
    out_enc[(size_t)r * 512 + bi] = 1.0f;

    red[tid] = sse;
    __syncthreads();
    for (int s = 128; s > 0; s >>= 1) {
        if (tid < s) red[tid] += red[tid + s];
        __syncthreads();
    }
    if (tid == 0) g_partial[blockIdx.x] = red[0];

    for (int i = tid; i < 512; i += 256)
        if (hist[i]) atomicAdd(&g_counts[i], hist[i]);
}

__global__ void vq_final(float* __restrict__ d_out)
{
    __shared__ float sh[512];
    int t = threadIdx.x;
    float avg = (float)g_counts[t] * (1.0f / 65536.0f);
    sh[t] = avg * logf(avg + 1e-10f);
    __syncthreads();
    for (int s = 256; s > 0; s >>= 1) {
        if (t < s) sh[t] += sh[t + s];
        __syncthreads();
    }
    if (t == 0) {
        d_out[OFF_PERP] = expf(-sh[0]);
        double acc = 0.0;
        for (int i = 0; i < 256; ++i) acc += (double)g_partial[i];
        d_out[0] = (float)(1.25 * acc / (65536.0 * 64.0));
    }
}

// ---------------- host launcher ----------------
static inline int grd(long long total) { return (int)((total + 255) / 256); }

extern "C" void kernel_launch(void* const* d_in, const int* in_sizes, int n_in,
                              void* d_out_v, int out_size)
{
    const float* x    = (const float*)d_in[0];
    const float* ew1  = (const float*)d_in[1];
    const float* eb1  = (const float*)d_in[2];
    const float* ew2  = (const float*)d_in[3];
    const float* eb2  = (const float*)d_in[4];
    const float* ew3  = (const float*)d_in[5];
    const float* eb3  = (const float*)d_in[6];
    const float* er1a = (const float*)d_in[7];
    const float* er1b = (const float*)d_in[8];
    const float* er2a = (const float*)d_in[9];
    const float* er2b = (const float*)d_in[10];
    const float* pwW  = (const float*)d_in[11];
    const float* pb   = (const float*)d_in[12];
    const float* cb   = (const float*)d_in[13];
    const float* dw1  = (const float*)d_in[14];
    const float* db1  = (const float*)d_in[15];
    const float* dr1a = (const float*)d_in[16];
    const float* dr1b = (const float*)d_in[17];
    const float* dr2a = (const float*)d_in[18];
    const float* dr2b = (const float*)d_in[19];
    const float* dtw1 = (const float*)d_in[20];
    const float* dtb1 = (const float*)d_in[21];
    const float* dtw2 = (const float*)d_in[22];
    const float* dtb2 = (const float*)d_in[23];
    float* d_out = (float*)d_out_v;

    void* p;
    float *h1, *a, *b, *c, *z, *q;
    cudaGetSymbolAddress(&p, g_h1); h1 = (float*)p;
    cudaGetSymbolAddress(&p, g_a);  a  = (float*)p;
    cudaGetSymbolAddress(&p, g_b);  b  = (float*)p;
    cudaGetSymbolAddress(&p, g_c);  c  = (float*)p;
    cudaGetSymbolAddress(&p, g_z);  z  = (float*)p;
    cudaGetSymbolAddress(&p, g_q);  q  = (float*)p;

    // ---- encoder ----
    ew1_t<<<dim3(16,16,8), 256>>>(x, ew1, eb1, h1);
    conv4s2_t<<<dim3(8,16,16), 256>>>(h1, ew2, eb2, a);
    conv3_t<128,false,false,true><<<dim3(8,16,16), 256>>>(a, ew3, eb3, b, 128);
    conv3_t<128,true, false,false><<<dim3(8,16,4), 256>>>(b, er1a, nullptr, c, 32);
    conv1x1_t<32,true,false,true><<<dim3(16,16,8), 256>>>(c, er1b, nullptr, b, a, 128);
    conv3_t<128,true, false,false><<<dim3(8,16,4), 256>>>(a, er2a, nullptr, c, 32);
    conv1x1_t<32,true,false,true><<<dim3(16,16,8), 256>>>(c, er2b, nullptr, a, b, 128);
    conv1x1_t<128,true,true,false><<<dim3(16,16,4), 256>>>(b, pwW, pb, nullptr, z, 64);

    // ---- vector quantizer ----
    vq_prep<<<2, 256>>>(cb);
    fill_zero2<<<grd(16777216), 256>>>((float2*)(d_out + OFF_ENC), 16777216);
    vq_main<<<256, 256>>>(cb, d_out + OFF_ENC, d_out + OFF_QUANT);
    vq_final<<<1, 512>>>(d_out);

    // ---- decoder ----
    conv3_t<64,false,false,true><<<dim3(8,16,16), 256>>>(q, dw1, db1, a, 128);
    conv3_t<128,true,false,false><<<dim3(8,16,4), 256>>>(a, dr1a, nullptr, c, 32);
    conv1x1_t<32,true,false,true><<<dim3(16,16,8), 256>>>(c, dr1b, nullptr, a, b, 128);
    conv3_t<128,true,false,false><<<dim3(8,16,4), 256>>>(b, dr2a, nullptr, c, 32);
    conv1x1_t<32,true,false,true><<<dim3(16,16,8), 256>>>(c, dr2b, nullptr, b, a, 128);
    convT1_t<<<dim3(8,16,32), 256>>>(a, dtw1, dtb1, h1);
    convT2_t<<<dim3(16,16,2), 256>>>(h1, dtw2, dtb2, d_out + OFF_XREC);
}

// round 16
// speedup vs baseline: 1.1754x; 1.1754x over previous
#include <cuda_runtime.h>
#include <math.h>

// ---------------- packed f32x2 helpers (sm_103a FFMA2) ----------------
typedef unsigned long long u64;
__device__ __forceinline__ u64 pk2(float lo, float hi) {
    u64 r; asm("mov.b64 %0, {%1,%2};" : "=l"(r) : "f"(lo), "f"(hi)); return r;
}
__device__ __forceinline__ u64 ffma2(u64 a, u64 b, u64 c) {
    u64 d; asm("fma.rn.f32x2 %0, %1, %2, %3;" : "=l"(d) : "l"(a), "l"(b), "l"(c)); return d;
}
__device__ __forceinline__ float2 upk2(u64 v) {
    float2 f; asm("mov.b64 {%0,%1}, %2;" : "=f"(f.x), "=f"(f.y) : "l"(v)); return f;
}

// ---------------- static device scratch ----------------
__device__ float g_h1[(size_t)16*64*128*128];
__device__ float g_a [(size_t)16*128*64*64];
__device__ float g_b [(size_t)16*128*64*64];
__device__ float g_c [(size_t)16*32*64*64];
__device__ float g_z [(size_t)16*64*64*64];
__device__ float g_c2[512];
__device__ int   g_counts[512];
__device__ float g_partial[256];

#define OFF_XREC   1
#define OFF_PERP   1048577
#define OFF_ENC    1048578
#define OFF_QUANT  34603010

// ============ 3x3 s1 p1 conv on 64x64; 8-row tile; thread = 2 rows x 8 oc ============
// weights smem [ci][tap(9)][o(8)]; FFMA2 over (o even, o odd) pairs.
// Staging geometry (r,c,valid) hoisted out of the ci loop: only the channel base moves.
// Per-output chain: bias -> ci asc -> tap asc (bit-exact across rounds).
template<int CIN, bool RELU_IN, bool RELU_OUT, bool HAS_BIAS>
__global__ __launch_bounds__(256)
void conv3_t(const float* __restrict__ in, const float* __restrict__ w,
             const float* __restrict__ bias, float* __restrict__ out, int COUT)
{
    __shared__ float s_in[2][10*66];
    __shared__ __align__(16) float s_w[CIN*72];
    const int tid = threadIdx.x;
    const int tx = tid & 63, ty = tid >> 6;
    const int tile = blockIdx.x, n = blockIdx.y, ocg = blockIdx.z;

    for (int i = tid; i < CIN*72; i += 256) {
        int ci = i / 72, rem = i % 72, tap = rem >> 3, o = rem & 7;
        s_w[i] = w[((size_t)(ocg*8 + o) * CIN + ci) * 9 + tap];
    }
    const int ih0 = tile*8 - 1;
    const float* inN = in + (size_t)n * CIN * 4096;

    // hoisted staging offsets: elements tid, tid+256, tid+512 (660 total)
    int eoff[3];
#pragma unroll
    for (int k = 0; k < 3; ++k) {
        int i = tid + k*256;
        int r = i / 66, c = i % 66;
        int ih = ih0 + r, iw = c - 1;
        bool ok = (i < 660) && ((unsigned)ih < 64u) && ((unsigned)iw < 64u);
        eoff[k] = ok ? (ih*64 + iw) : -1;
    }

    {   // stage ci 0
        float* sb = s_in[0];
#pragma unroll
        for (int k = 0; k < 3; ++k) {
            if (k < 2 || tid < 148) {
                float v = (eoff[k] >= 0) ? inN[eoff[k]] : 0.0f;
                if (RELU_IN) v = fmaxf(v, 0.0f);
                sb[tid + k*256] = v;
            }
        }
    }
    __syncthreads();

    u64 accp[2][4];  // [j][pair p], pair p covers o = 2p, 2p+1
#pragma unroll
    for (int p = 0; p < 4; ++p) {
        float b0 = HAS_BIAS ? __ldg(&bias[ocg*8+2*p])   : 0.0f;
        float b1 = HAS_BIAS ? __ldg(&bias[ocg*8+2*p+1]) : 0.0f;
        u64 bp = pk2(b0, b1);
        accp[0][p] = bp; accp[1][p] = bp;
    }

#pragma unroll 1
    for (int ci = 0; ci < CIN; ++ci) {
        if (ci + 1 < CIN) {
            const float* ip = inN + (size_t)(ci+1) * 4096;
            float* sb = s_in[(ci+1)&1];
#pragma unroll
            for (int k = 0; k < 3; ++k) {
                if (k < 2 || tid < 148) {
                    float v = (eoff[k] >= 0) ? ip[eoff[k]] : 0.0f;
                    if (RELU_IN) v = fmaxf(v, 0.0f);
                    sb[tid + k*256] = v;
                }
            }
        }
        const float* sb = s_in[ci&1];
        u64 ivp[12];
#pragma unroll
        for (int r = 0; r < 4; ++r)
#pragma unroll
            for (int c = 0; c < 3; ++c) {
                float v = sb[(ty*2+r)*66 + tx + c];
                ivp[r*3+c] = pk2(v, v);
            }
        const float* wp = s_w + ci*72;
#pragma unroll
        for (int t = 0; t < 9; ++t) {
            ulonglong2 wA = *(const ulonglong2*)(wp + t*8);      // pairs (o0,o1),(o2,o3)
            ulonglong2 wB = *(const ulonglong2*)(wp + t*8 + 4);  // pairs (o4,o5),(o6,o7)
            const int r = t / 3, c = t % 3;
#pragma unroll
            for (int j = 0; j < 2; ++j) {
                u64 vv = ivp[(j+r)*3+c];
                accp[j][0] = ffma2(vv, wA.x, accp[j][0]);
                accp[j][1] = ffma2(vv, wA.y, accp[j][1]);
                accp[j][2] = ffma2(vv, wB.x, accp[j][2]);
                accp[j][3] = ffma2(vv, wB.y, accp[j][3]);
            }
        }
        __syncthreads();
    }

    const int ohb = tile*8 + ty*2;
#pragma unroll
    for (int j = 0; j < 2; ++j)
#pragma unroll
        for (int p = 0; p < 4; ++p) {
            float2 v = upk2(accp[j][p]);
            if (RELU_OUT) { v.x = fmaxf(v.x, 0.0f); v.y = fmaxf(v.y, 0.0f); }
            out[(((size_t)n * COUT + ocg*8+2*p)   * 64 + ohb + j) * 64 + tx] = v.x;
            out[(((size_t)n * COUT + ocg*8+2*p+1) * 64 + ohb + j) * 64 + tx] = v.y;
        }
}

// ============ 4x4 s2 p1 conv, 64ch 128x128 -> 128ch 64x64 (ew2) ============
// weight staging [tap(16)][o(8)]; FFMA2 over o-pairs; hoisted staging offsets
__global__ __launch_bounds__(256)
void conv4s2_t(const float* __restrict__ in, const float* __restrict__ w,
               const float* __restrict__ bias, float* __restrict__ out)
{
    __shared__ float s_in[2][18*130];
    __shared__ __align__(16) float s_wc[2][128];
    const int tid = threadIdx.x;
    const int tx = tid & 63, ty = tid >> 6;
    const int tile = blockIdx.x, n = blockIdx.y, ocg = blockIdx.z;
    const int ih0 = 16*tile - 1;
    const float* inN = in + (size_t)n * 64 * 16384;

    // 18*130 = 2340 elements; k<9 full, k=9 partial (tid<36)
    int eoff[10];
#pragma unroll
    for (int k = 0; k < 10; ++k) {
        int i = tid + k*256;
        int r = i / 130, c = i % 130;
        int ih = ih0 + r, iw = c - 1;
        bool ok = (k < 9 || tid < 36) && ((unsigned)ih < 128u) && ((unsigned)iw < 128u);
        eoff[k] = ok ? (ih*128 + iw) : -1;
    }

    {   // stage ci 0
        float* sb = s_in[0];
#pragma unroll
        for (int k = 0; k < 10; ++k)
            if (k < 9 || tid < 36)
                sb[tid + k*256] = (eoff[k] >= 0) ? inN[eoff[k]] : 0.0f;
    }
    if (tid < 128) {
        int tap = tid >> 3, o = tid & 7;
        s_wc[0][tid] = w[((size_t)(ocg*8 + o) * 64 + 0) * 16 + tap];
    }
    __syncthreads();

    u64 accp[2][4];
#pragma unroll
    for (int p = 0; p < 4; ++p) {
        u64 bp = pk2(__ldg(&bias[ocg*8+2*p]), __ldg(&bias[ocg*8+2*p+1]));
        accp[0][p] = bp; accp[1][p] = bp;
    }

#pragma unroll 1
    for (int ci = 0; ci < 64; ++ci) {
        if (ci + 1 < 64) {
            const float* ip = inN + (size_t)(ci+1) * 16384;
            float* sb = s_in[(ci+1)&1];
#pragma unroll
            for (int k = 0; k < 10; ++k)
                if (k < 9 || tid < 36)
                    sb[tid + k*256] = (eoff[k] >= 0) ? ip[eoff[k]] : 0.0f;
            if (tid < 128) {
                int tap = tid >> 3, o = tid & 7;
                s_wc[(ci+1)&1][tid] = w[((size_t)(ocg*8 + o) * 64 + ci+1) * 16 + tap];
            }
        }
        const float* sb = s_in[ci&1];
        const float* wc = s_wc[ci&1];
#pragma unroll
        for (int kh = 0; kh < 4; ++kh) {
            u64 ivp[8];
#pragma unroll
            for (int j = 0; j < 2; ++j)
#pragma unroll
                for (int kw = 0; kw < 4; ++kw) {
                    float v = sb[(2*(ty*2+j)+kh)*130 + 2*tx + kw];
                    ivp[j*4+kw] = pk2(v, v);
                }
#pragma unroll
            for (int kw = 0; kw < 4; ++kw) {
                const int t = kh*4 + kw;
                ulonglong2 wA = *(const ulonglong2*)(wc + t*8);
                ulonglong2 wB = *(const ulonglong2*)(wc + t*8 + 4);
#pragma unroll
                for (int j = 0; j < 2; ++j) {
                    u64 vv = ivp[j*4+kw];
                    accp[j][0] = ffma2(vv, wA.x, accp[j][0]);
                    accp[j][1] = ffma2(vv, wA.y, accp[j][1]);
                    accp[j][2] = ffma2(vv, wB.x, accp[j][2]);
                    accp[j][3] = ffma2(vv, wB.y, accp[j][3]);
                }
            }
        }
        __syncthreads();
    }

    const int ohb = tile*8 + ty*2;
#pragma unroll
    for (int j = 0; j < 2; ++j)
#pragma unroll
        for (int p = 0; p < 4; ++p) {
            float2 v = upk2(accp[j][p]);
            out[(((size_t)n * 128 + ocg*8+2*p)   * 64 + ohb + j) * 64 + tx] = fmaxf(v.x, 0.0f);
            out[(((size_t)n * 128 + ocg*8+2*p+1) * 64 + ohb + j) * 64 + tx] = fmaxf(v.y, 0.0f);
        }
}

// ============ 4x4 s2 p1 conv, 1ch 256x256 -> 64ch 128x128 (ew1) ============
__global__ __launch_bounds__(256)
void ew1_t(const float* __restrict__ in, const float* __restrict__ w,
           const float* __restrict__ bias, float* __restrict__ out)
{
    __shared__ float s_in[34*130];
    __shared__ float s_w[128];
    const int tid = threadIdx.x;
    const int tx = tid & 63, ty = tid >> 6;
    const int rt = blockIdx.x >> 1, ct = blockIdx.x & 1;
    const int n = blockIdx.y, ocg = blockIdx.z;
    const int ih0 = 32*rt - 1, iw0 = 128*ct - 1;
    const float* ip = in + (size_t)n * 65536;

    for (int i = tid; i < 34*130; i += 256) {
        int r = i / 130, c = i % 130;
        int ih = ih0 + r, iw = iw0 + c;
        s_in[i] = ((unsigned)ih < 256u && (unsigned)iw < 256u) ? ip[ih*256+iw] : 0.0f;
    }
    if (tid < 128) s_w[tid] = w[(ocg*8 + (tid>>4))*16 + (tid&15)];
    __syncthreads();

    float acc[32];
#pragma unroll
    for (int o = 0; o < 8; ++o) {
        float b0 = __ldg(&bias[ocg*8+o]);
#pragma unroll
        for (int j = 0; j < 4; ++j) acc[j*8+o] = b0;
    }
#pragma unroll
    for (int kh = 0; kh < 4; ++kh) {
        float iv[16];
#pragma unroll
        for (int j = 0; j < 4; ++j)
#pragma unroll
            for (int kw = 0; kw < 4; ++kw)
                iv[j*4+kw] = s_in[(2*(ty*4+j)+kh)*130 + 2*tx + kw];
#pragma unroll
        for (int o = 0; o < 8; ++o) {
            float v0 = s_w[o*16+kh*4+0], v1 = s_w[o*16+kh*4+1],
                  v2 = s_w[o*16+kh*4+2], v3 = s_w[o*16+kh*4+3];
#pragma unroll
            for (int j = 0; j < 4; ++j) {
                float a = acc[j*8+o];
                a = fmaf(iv[j*4+0], v0, a);
                a = fmaf(iv[j*4+1], v1, a);
                a = fmaf(iv[j*4+2], v2, a);
                a = fmaf(iv[j*4+3], v3, a);
                acc[j*8+o] = a;
            }
        }
    }
    const int ohb = rt*16 + ty*4;
#pragma unroll
    for (int j = 0; j < 4; ++j)
#pragma unroll
        for (int o = 0; o < 8; ++o)
            out[(((size_t)n * 64 + ocg*8+o) * 128 + ohb + j) * 128 + ct*64 + tx] = fmaxf(acc[j*8+o], 0.0f);
}

// ============ convT 4x4 s2 p1, 128ch 64x64 -> 64ch 128x128 (dtw1) ============
// weights [ci][tap(8)][o(8)]; thread = 2 class rows x 2 px x 8 oc; FFMA2 over o-pairs
// (OCG=8 form, validated in an earlier passing round); hoisted staging offsets
__global__ __launch_bounds__(256)
void convT1_t(const float* __restrict__ in, const float* __restrict__ w,
              const float* __restrict__ bias, float* __restrict__ out)
{
    __shared__ float s_in[2][10*66];
    __shared__ __align__(16) float s_w[128*64];
    const int tid = threadIdx.x;
    const int tx = tid & 63, ty = tid >> 6;
    const int tile = blockIdx.x, n = blockIdx.y;
    const int py = blockIdx.z & 1, ocg = blockIdx.z >> 1;

    for (int i = tid; i < 128*64; i += 256) {
        int ci = i >> 6, rem = i & 63, tap = rem >> 3, o = rem & 7;
        int a = tap >> 2, kw = tap & 3;
        int kh = py ? (a ? 0 : 2) : (a ? 1 : 3);
        s_w[i] = w[((size_t)ci * 64 + ocg*8 + o) * 16 + kh*4 + kw];
    }
    const int ih0 = tile*8 - 1;
    const float* inN = in + (size_t)n * 128 * 4096;

    int eoff[3];
#pragma unroll
    for (int k = 0; k < 3; ++k) {
        int i = tid + k*256;
        int r = i / 66, c = i % 66;
        int ih = ih0 + r, iw = c - 1;
        bool ok = (i < 660) && ((unsigned)ih < 64u) && ((unsigned)iw < 64u);
        eoff[k] = ok ? (ih*64 + iw) : -1;
    }

    {   // stage ci 0
        float* sb = s_in[0];
#pragma unroll
        for (int k = 0; k < 3; ++k)
            if (k < 2 || tid < 148)
                sb[tid + k*256] = (eoff[k] >= 0) ? inN[eoff[k]] : 0.0f;
    }
    __syncthreads();

    u64 accp[4][4]; // [(j*2+px)][pair p], p covers o = 2p, 2p+1
#pragma unroll
    for (int p = 0; p < 4; ++p) {
        u64 bp = pk2(__ldg(&bias[ocg*8+2*p]), __ldg(&bias[ocg*8+2*p+1]));
#pragma unroll
        for (int jp = 0; jp < 4; ++jp) accp[jp][p] = bp;
    }

#pragma unroll 1
    for (int ci = 0; ci < 128; ++ci) {
        if (ci + 1 < 128) {
            const float* ip = inN + (size_t)(ci+1) * 4096;
            float* sb = s_in[(ci+1)&1];
#pragma unroll
            for (int k = 0; k < 3; ++k)
                if (k < 2 || tid < 148)
                    sb[tid + k*256] = (eoff[k] >= 0) ? ip[eoff[k]] : 0.0f;
        }
        const float* sb = s_in[ci&1];
        const int rb = ty*2 + py;
        u64 ivp[9];
#pragma unroll
        for (int r = 0; r < 3; ++r)
#pragma unroll
            for (int c = 0; c < 3; ++c) {
                float v = sb[(rb+r)*66 + tx + c];
                ivp[r*3+c] = pk2(v, v);
            }
        const float* wp = s_w + ci*64;
#pragma unroll
        for (int tap = 0; tap < 8; ++tap) {
            const int a = tap >> 2, kw = tap & 3;
            const int px  = (kw & 1) ? 0 : 1;
            const int col = (kw & 1) ? ((3-kw) >> 1) : ((2-kw) >> 1) + 1;
            ulonglong2 wA = *(const ulonglong2*)(wp + tap*8);
            ulonglong2 wB = *(const ulonglong2*)(wp + tap*8 + 4);
#pragma unroll
            for (int j = 0; j < 2; ++j) {
                u64 vv = ivp[(j+a)*3 + col];
                accp[j*2+px][0] = ffma2(vv, wA.x, accp[j*2+px][0]);
                accp[j*2+px][1] = ffma2(vv, wA.y, accp[j*2+px][1]);
                accp[j*2+px][2] = ffma2(vv, wB.x, accp[j*2+px][2]);
                accp[j*2+px][3] = ffma2(vv, wB.y, accp[j*2+px][3]);
            }
        }
        __syncthreads();
    }

#pragma unroll
    for (int j = 0; j < 2; ++j) {
        int oh = 2*(tile*8 + ty*2 + j) + py;
        float vx0[8], vx1[8];
#pragma unroll
        for (int p = 0; p < 4; ++p) {
            float2 v0 = upk2(accp[j*2+0][p]);
            float2 v1 = upk2(accp[j*2+1][p]);
            vx0[2*p] = v0.x; vx0[2*p+1] = v0.y;
            vx1[2*p] = v1.x; vx1[2*p+1] = v1.y;
        }
#pragma unroll
        for (int o = 0; o < 8; ++o) {
            float2 v;
            v.x = fmaxf(vx0[o], 0.0f);
            v.y = fmaxf(vx1[o], 0.0f);
            *(float2*)&out[(((size_t)n * 64 + ocg*8+o) * 128 + oh) * 128 + 2*tx] = v;
        }
    }
}

// ============ convT 4x4 s2 p1, 64ch 128x128 -> 1ch 256x256 (dtw2) ============
__global__ __launch_bounds__(256)
void convT2_t(const float* __restrict__ in, const float* __restrict__ w,
              const float* __restrict__ bias, float* __restrict__ out)
{
    __shared__ float s_in[2][10*130];
    __shared__ __align__(16) float s_w[64*8];
    const int tid = threadIdx.x;
    const int tx = tid & 127, ty = tid >> 7;
    const int tile = blockIdx.x, n = blockIdx.y, py = blockIdx.z;

    for (int i = tid; i < 64*8; i += 256) {
        int ci = i >> 3, a = (i >> 2) & 1, kw = i & 3;
        int kh = py ? (a ? 0 : 2) : (a ? 1 : 3);
        s_w[i] = w[(size_t)ci * 16 + kh*4 + kw];
    }
    const int ih0 = tile*8 - 1;
    const float* inN = in + (size_t)n * 64 * 16384;

    // 10*130 = 1300 elements; k<5 full, k=5 partial (tid<20)
    int eoff[6];
#pragma unroll
    for (int k = 0; k < 6; ++k) {
        int i = tid + k*256;
        int r = i / 130, c = i % 130;
        int ih = ih0 + r, iw = c - 1;
        bool ok = (k < 5 || tid < 20) && ((unsigned)ih < 128u) && ((unsigned)iw < 128u);
        eoff[k] = ok ? (ih*128 + iw) : -1;
    }

    {   // stage ci 0
        float* sb = s_in[0];
#pragma unroll
        for (int k = 0; k < 6; ++k)
            if (k < 5 || tid < 20)
                sb[tid + k*256] = (eoff[k] >= 0) ? inN[eoff[k]] : 0.0f;
    }
    __syncthreads();

    float b0 = __ldg(&bias[0]);
    float acc[8];
#pragma unroll
    for (int i = 0; i < 8; ++i) acc[i] = b0;

#pragma unroll 1
    for (int ci = 0; ci < 64; ++ci) {
        if (ci + 1 < 64) {
            const float* ip = inN + (size_t)(ci+1) * 16384;
            float* sb = s_in[(ci+1)&1];
#pragma unroll
            for (int k = 0; k < 6; ++k)
                if (k < 5 || tid < 20)
                    sb[tid + k*256] = (eoff[k] >= 0) ? ip[eoff[k]] : 0.0f;
        }
        const float* sb = s_in[ci&1];
        const int rb = ty*4 + py;
        float iv[15];
#pragma unroll
        for (int r = 0; r < 5; ++r)
#pragma unroll
            for (int c = 0; c < 3; ++c)
                iv[r*3+c] = sb[(rb+r)*130 + tx + c];
        float4 lv = *(const float4*)(s_w + ci*8);
        float4 hv = *(const float4*)(s_w + ci*8 + 4);
#pragma unroll
        for (int j = 0; j < 4; ++j) {
            float a0 = acc[j*2+0];
            a0 = fmaf(iv[j*3+0],     lv.w, a0);
            a0 = fmaf(iv[j*3+1],     lv.y, a0);
            a0 = fmaf(iv[(j+1)*3+0], hv.w, a0);
            a0 = fmaf(iv[(j+1)*3+1], hv.y, a0);
            acc[j*2+0] = a0;
            float a1 = acc[j*2+1];
            a1 = fmaf(iv[j*3+1],     lv.z, a1);
            a1 = fmaf(iv[j*3+2],     lv.x, a1);
            a1 = fmaf(iv[(j+1)*3+1], hv.z, a1);
            a1 = fmaf(iv[(j+1)*3+2], hv.x, a1);
            acc[j*2+1] = a1;
        }
        __syncthreads();
    }

#pragma unroll
    for (int j = 0; j < 4; ++j) {
        int oh = 2*(tile*8 + ty*4 + j) + py;
        size_t base = (size_t)n * 65536 + (size_t)oh * 256 + 2*tx;
        out[base]     = acc[j*2+0];
        out[base + 1] = acc[j*2+1];
    }
}

// ============ 1x1 conv; thread = 1 px x 16 oc; FFMA2 over o-pairs ============
template<int CIN, bool RELU_IN, bool HAS_BIAS, bool ADD_RES>
__global__ __launch_bounds__(256)
void conv1x1_t(const float* __restrict__ in, const float* __restrict__ w,
               const float* __restrict__ bias, const float* __restrict__ res,
               float* __restrict__ out, int COUT)
{
    __shared__ __align__(16) float s_w[CIN*16];
    const int tid = threadIdx.x;
    const int n = blockIdx.y, ocg = blockIdx.z;
    for (int i = tid; i < CIN*16; i += 256)
        s_w[i] = w[(size_t)(ocg*16 + (i&15)) * CIN + (i>>4)];
    __syncthreads();

    const int hw = blockIdx.x*256 + tid;
    u64 accp[8];
#pragma unroll
    for (int p = 0; p < 8; ++p) {
        float b0 = HAS_BIAS ? __ldg(&bias[ocg*16+2*p])   : 0.0f;
        float b1 = HAS_BIAS ? __ldg(&bias[ocg*16+2*p+1]) : 0.0f;
        accp[p] = pk2(b0, b1);
    }
    const float* ip = in + ((size_t)n * CIN << 12) + hw;
#pragma unroll 4
    for (int ci = 0; ci < CIN; ++ci) {
        float v = ip[(size_t)ci << 12];
        if (RELU_IN) v = fmaxf(v, 0.0f);
        u64 vv = pk2(v, v);
        const ulonglong2* wr = (const ulonglong2*)(s_w + ci*16);
        ulonglong2 w0 = wr[0], w1 = wr[1], w2 = wr[2], w3 = wr[3];
        accp[0] = ffma2(vv, w0.x, accp[0]);
        accp[1] = ffma2(vv, w0.y, accp[1]);
        accp[2] = ffma2(vv, w1.x, accp[2]);
        accp[3] = ffma2(vv, w1.y, accp[3]);
        accp[4] = ffma2(vv, w2.x, accp[4]);
        accp[5] = ffma2(vv, w2.y, accp[5]);
        accp[6] = ffma2(vv, w3.x, accp[6]);
        accp[7] = ffma2(vv, w3.y, accp[7]);
    }
#pragma unroll
    for (int p = 0; p < 8; ++p) {
        float2 v = upk2(accp[p]);
        size_t oi0 = (((size_t)n * COUT + ocg*16+2*p)   << 12) + hw;
        size_t oi1 = (((size_t)n * COUT + ocg*16+2*p+1) << 12) + hw;
        float v0 = v.x, v1 = v.y;
        if (ADD_RES) { v0 += res[oi0]; v1 += res[oi1]; }
        out[oi0] = v0;
        out[oi1] = v1;
    }
}

// ---------------- VQ ----------------
__global__ void vq_prep(const float* __restrict__ cb)
{
    int k = blockIdx.x * blockDim.x + threadIdx.x;
    if (k < 512) {
        float s = 0.0f;
        const float* c = cb + k * 64;
#pragma unroll
        for (int d = 0; d < 64; ++d) s = fmaf(c[d], c[d], s);
        g_c2[k] = s;
        g_counts[k] = 0;
    }
}

__global__ void fill_zero2(float2* __restrict__ p, int n2)
{
    int i = blockIdx.x * blockDim.x + threadIdx.x;
    if (i < n2) p[i] = make_float2(0.0f, 0.0f);
}

// merged argmin + quantize (bit-exact tie-break preserved).
// quantized is written ONLY to d_out's quantized region; decoder reads it there.
__global__ void vq_main(const float* __restrict__ cb, float* __restrict__ out_enc,
                        float* __restrict__ out_quant)
{
    __shared__ float sc[64 * 64];
    __shared__ float sc2[64];
    __shared__ int   hist[512];
    __shared__ float red[256];
    int tid = threadIdx.x;
    for (int i = tid; i < 512; i += 256) hist[i] = 0;

    int r  = blockIdx.x * 256 + tid;
    int n  = r >> 12;
    int hw = r & 4095;
    size_t zbase = (size_t)n * 64 * 4096 + hw;
    const float* zp = g_z + zbase;

    float zr[64];
#pragma unroll
    for (int d = 0; d < 64; ++d) zr[d] = zp[(size_t)d * 4096];

    float z2 = 0.0f;
#pragma unroll
    for (int d = 0; d < 64; ++d) z2 = fmaf(zr[d], zr[d], z2);

    float best = 3.4e38f;
    int bi = 0;
    for (int chunk = 0; chunk < 8; ++chunk) {
        __syncthreads();
        for (int i = tid; i < 4096; i += 256) sc[i] = cb[chunk * 4096 + i];
        if (tid < 64) sc2[tid] = g_c2[chunk * 64 + tid];
        __syncthreads();
        for (int c = 0; c < 64; ++c) {
            const float4* cv = (const float4*)&sc[c * 64];
            float d0 = 0, d1 = 0, d2 = 0, d3 = 0;
#pragma unroll
            for (int j = 0; j < 16; ++j) {
                float4 v = cv[j];
                d0 = fmaf(v.x, zr[4 * j + 0], d0);
                d1 = fmaf(v.y, zr[4 * j + 1], d1);
                d2 = fmaf(v.z, zr[4 * j + 2], d2);
                d3 = fmaf(v.w, zr[4 * j + 3], d3);
            }
            float dot = (d0 + d1) + (d2 + d3);
            float dist = __fadd_rn(__fadd_rn(z2, sc2[c]), -2.0f * dot);
            if (dist < best) { best = dist; bi = chunk * 64 + c; }
        }
    }
    atomicAdd(&hist[bi], 1);

    float* oq = out_quant + zbase;
    const float* ck = cb + bi * 64;
    float sse = 0.0f;
#pragma unroll
    for (int d = 0; d < 64; ++d) {
        float qv = __ldg(&ck[d]);
        oq[(size_t)d * 4096] = qv;
        float df = qv - zr[d];
        sse = fmaf(df, df, sse);
    }
    out_enc[(size_t)r * 512 + bi] = 1.0f;

    red[tid] = sse;
    __syncthreads();
    for (int s = 128; s > 0; s >>= 1) {
        if (tid < s) red[tid] += red[tid + s];
        __syncthreads();
    }
    if (tid == 0) g_partial[blockIdx.x] = red[0];

    for (int i = tid; i < 512; i += 256)
        if (hist[i]) atomicAdd(&g_counts[i], hist[i]);
}

__global__ void vq_final(float* __restrict__ d_out)
{
    __shared__ float sh[512];
    int t = threadIdx.x;
    float avg = (float)g_counts[t] * (1.0f / 65536.0f);
    sh[t] = avg * logf(avg + 1e-10f);
    __syncthreads();
    for (int s = 256; s > 0; s >>= 1) {
        if (t < s) sh[t] += sh[t + s];
        __syncthreads();
    }
    if (t == 0) {
        d_out[OFF_PERP] = expf(-sh[0]);
        double acc = 0.0;
        for (int i = 0; i < 256; ++i) acc += (double)g_partial[i];
        d_out[0] = (float)(1.25 * acc / (65536.0 * 64.0));
    }
}

// ---------------- host launcher ----------------
static inline int grd(long long total) { return (int)((total + 255) / 256); }

extern "C" void kernel_launch(void* const* d_in, const int* in_sizes, int n_in,
                              void* d_out_v, int out_size)
{
    const float* x    = (const float*)d_in[0];
    const float* ew1  = (const float*)d_in[1];
    const float* eb1  = (const float*)d_in[2];
    const float* ew2  = (const float*)d_in[3];
    const float* eb2  = (const float*)d_in[4];
    const float* ew3  = (const float*)d_in[5];
    const float* eb3  = (const float*)d_in[6];
    const float* er1a = (const float*)d_in[7];
    const float* er1b = (const float*)d_in[8];
    const float* er2a = (const float*)d_in[9];
    const float* er2b = (const float*)d_in[10];
    const float* pwW  = (const float*)d_in[11];
    const float* pb   = (const float*)d_in[12];
    const float* cb   = (const float*)d_in[13];
    const float* dw1  = (const float*)d_in[14];
    const float* db1  = (const float*)d_in[15];
    const float* dr1a = (const float*)d_in[16];
    const float* dr1b = (const float*)d_in[17];
    const float* dr2a = (const float*)d_in[18];
    const float* dr2b = (const float*)d_in[19];
    const float* dtw1 = (const float*)d_in[20];
    const float* dtb1 = (const float*)d_in[21];
    const float* dtw2 = (const float*)d_in[22];
    const float* dtb2 = (const float*)d_in[23];
    float* d_out = (float*)d_out_v;

    void* p;
    float *h1, *a, *b, *c, *z;
    cudaGetSymbolAddress(&p, g_h1); h1 = (float*)p;
    cudaGetSymbolAddress(&p, g_a);  a  = (float*)p;
    cudaGetSymbolAddress(&p, g_b);  b  = (float*)p;
    cudaGetSymbolAddress(&p, g_c);  c  = (float*)p;
    cudaGetSymbolAddress(&p, g_z);  z  = (float*)p;
    float* q = d_out + OFF_QUANT;   // quantized lives directly in the output buffer

    // ---- encoder ----
    ew1_t<<<dim3(16,16,8), 256>>>(x, ew1, eb1, h1);
    conv4s2_t<<<dim3(8,16,16), 256>>>(h1, ew2, eb2, a);
    conv3_t<128,false,false,true><<<dim3(8,16,16), 256>>>(a, ew3, eb3, b, 128);
    conv3_t<128,true, false,false><<<dim3(8,16,4), 256>>>(b, er1a, nullptr, c, 32);
    conv1x1_t<32,true,false,true><<<dim3(16,16,8), 256>>>(c, er1b, nullptr, b, a, 128);
    conv3_t<128,true, false,false><<<dim3(8,16,4), 256>>>(a, er2a, nullptr, c, 32);
    conv1x1_t<32,true,false,true><<<dim3(16,16,8), 256>>>(c, er2b, nullptr, a, b, 128);
    conv1x1_t<128,true,true,false><<<dim3(16,16,4), 256>>>(b, pwW, pb, nullptr, z, 64);

    // ---- vector quantizer ----
    vq_prep<<<2, 256>>>(cb);
    fill_zero2<<<grd(16777216), 256>>>((float2*)(d_out + OFF_ENC), 16777216);
    vq_main<<<256, 256>>>(cb, d_out + OFF_ENC, q);
    vq_final<<<1, 512>>>(d_out);

    // ---- decoder ----
    conv3_t<64,false,false,true><<<dim3(8,16,16), 256>>>(q, dw1, db1, a, 128);
    conv3_t<128,true,false,false><<<dim3(8,16,4), 256>>>(a, dr1a, nullptr, c, 32);
    conv1x1_t<32,true,false,true><<<dim3(16,16,8), 256>>>(c, dr1b, nullptr, a, b, 128);
    conv3_t<128,true,false,false><<<dim3(8,16,4), 256>>>(b, dr2a, nullptr, c, 32);
    conv1x1_t<32,true,false,true><<<dim3(16,16,8), 256>>>(c, dr2b, nullptr, b, a, 128);
    convT1_t<<<dim3(8,16,16), 256>>>(a, dtw1, dtb1, h1);
    convT2_t<<<dim3(16,16,2), 256>>>(h1, dtw2, dtb2, d_out + OFF_XREC);
}